// round 16
// baseline (speedup 1.0000x reference)
#include <cuda_runtime.h>

// CapsNet dynamic routing, persistent kernel, round 16.
// = R15 EXACTLY (331.9us best: R9 compute path + minimal-fence barrier with
//   release-atomic arrival and acquire-load polling)
// + ONE change: the per-barrier ld.global of g_sense (a dependent ~300cyc L2
//   round trip on every CTA's arrival path) is removed. The generation is
//   tracked locally: base = g_sense read ONCE at kernel start, target =
//   base + ep with ep advanced uniformly at each of the 59 deterministic
//   barrier calls. The arrival RMW's increment is made data-dependent on
//   base via opaque asm so it cannot issue before the base load completes
//   (closes the issue-reorder window that today's per-barrier reload shared).

#define NCTA 144
#define THREADS 1024
#define KL 8
#define BATCH 512
#define JOUT 10
#define ITERS 3
#define SB 384          // b's with u_hat in smem
#define SQ 6            // smem chunks of 64 b
#define RQ 2            // register chunks of 64 b
#define NCH 8           // total chunks
#define UHB 128         // floats per b row (swizzled, no pad)
#define WTB 68          // w_t row stride
#define XST 20          // xs row stride (16B-aligned, low-conflict)

#define SMEM_FLOATS (SB*UHB + 4*64*XST + 2*16*WTB + KL*JOUT + KL + 1024)
#define SMEM_BYTES (SMEM_FLOATS * 4)

typedef unsigned long long ull;

__device__ float g_spart[NCTA * BATCH * 16];
__device__ float g_v[BATCH * 16];
__device__ unsigned g_count;
__device__ unsigned g_sense;

__device__ __forceinline__ ull f2_pk(float lo, float hi) {
    ull r; asm("mov.b64 %0,{%1,%2};" : "=l"(r) : "f"(lo), "f"(hi)); return r;
}
__device__ __forceinline__ float2 f2_up(ull a) {
    float2 r; asm("mov.b64 {%0,%1},%2;" : "=f"(r.x), "=f"(r.y) : "l"(a)); return r;
}
__device__ __forceinline__ ull f2_fma(ull a, ull b, ull c) {
    ull d; asm("fma.rn.f32x2 %0,%1,%2,%3;" : "=l"(d) : "l"(a), "l"(b), "l"(c)); return d;
}
__device__ __forceinline__ ull f2_mul(ull a, ull b) {
    ull d; asm("mul.rn.f32x2 %0,%1,%2;" : "=l"(d) : "l"(a), "l"(b)); return d;
}
__device__ __forceinline__ ull f2_add(ull a, ull b) {
    ull d; asm("add.rn.f32x2 %0,%1,%2;" : "=l"(d) : "l"(a), "l"(b)); return d;
}

// swizzled word offset of the h-th float4 (h=0: kl0-3, h=1: kl4-7) for vector idx u
__device__ __forceinline__ int uoff(int u, int h) { return (u * 8 + h * 4) ^ (u & 4); }

// Minimal grid barrier with locally-tracked generation.
// target: the sense value this barrier completes at (base + epoch).
// inc:    always 1, but data-dependent on the launch-start base read.
// Arrival: atom.add.release.gpu (after __syncthreads, covers all warps' writes).
// Flip:    count reset; __threadfence (cumulativity over the g_count RMW chain
//          -> all CTAs' prior writes); st.release of sense = target.
// Wait:    ld.acquire.gpu poll + nanosleep backoff (synchronizes with release).
// Monotonic sense + self-resetting count -> graph-replay safe.
__device__ __forceinline__ void grid_barrier(unsigned target, unsigned inc) {
    __syncthreads();
    if (threadIdx.x == 0) {
        unsigned old;
        asm volatile("atom.add.release.gpu.global.u32 %0, [%1], %2;"
                     : "=r"(old) : "l"(&g_count), "r"(inc) : "memory");
        if (old == NCTA - 1) {
            g_count = 0;
            __threadfence();
            asm volatile("st.release.gpu.global.u32 [%0], %1;"
                         :: "l"(&g_sense), "r"(target) : "memory");
        } else {
            unsigned s;
            for (;;) {
                asm volatile("ld.acquire.gpu.global.u32 %0, [%1];"
                             : "=r"(s) : "l"(&g_sense) : "memory");
                if ((int)(s - target) >= 0) break;
                __nanosleep(64);
            }
        }
    }
    __syncthreads();
}

__global__ void __launch_bounds__(THREADS, 1)
caps_routing_kernel(const float* __restrict__ x,   // [512,1152,8]
                    const float* __restrict__ W,   // [10,1152,8,16]
                    float* __restrict__ out)       // [512,10,16]
{
    extern __shared__ float sm[];
    float* uh_s    = sm;                     // SB*UHB
    float* xs      = uh_s + SB * UHB;        // 4-buffer x staging ring
    float* w_t0    = xs + 4 * 64 * XST;      // 2 x 16*WTB (double-buffered W)
    float* bs      = w_t0 + 2 * 16 * WTB;    // KL*JOUT b_IJ rows
    float* c_s     = bs + KL * JOUT;         // KL coupling coeffs
    float* scratch = c_s + KL;               // 1024 reduction scratch

    const int t    = threadIdx.x;
    const int cta  = blockIdx.x;
    const int k0   = cta * KL;
    const int u    = t & 15;
    const int bg   = t >> 4;                 // 0..63
    const int lane = t & 31;
    const int warp = t >> 5;

    ull uhr[RQ][4];                          // register u_hat for b in [384,512)

    // ---- read barrier base ONCE; derive inc=1 with an opaque data dependency
    //      on the load so the first arrival RMW cannot issue before it ----
    unsigned base = 0, inc = 1;
    if (t == 0) {
        asm volatile("ld.global.u32 %0, [%1];" : "=r"(base) : "l"(&g_sense));
        asm volatile("{ .reg .u32 z; and.b32 z, %1, 0; add.u32 %0, %0, z; }"
                     : "+r"(inc) : "r"(base));
    }
    unsigned ep = 0;

    for (int i = t; i < KL * JOUT; i += THREADS) bs[i] = 0.f;
    if (t < KL) c_s[t] = 0.1f;               // softmax(0) over 10
    __syncthreads();

    // per-thread x element address base: x[b=bg(+64*ch), k0.., qi*16+u]
    const float* xbase = x + ((size_t)bg * 1152 + k0) * 8 + u;
    #define XADDR(s_) (xbase + (size_t)((s_) & 7) * 64 * 9216 + ((s_) >> 3) * 16)
    #define XSLOT(p_) (xs + (((p_) * 64) + bg) * XST + u)

    // W transpose indices (KL*128 == THREADS: one element per thread per j)
    const int wkl = t >> 7, wrest = t & 127;
    const int wdstA = (wrest & 15) * WTB + wkl * 8 + (wrest >> 4);

    // ---- load W[j=0] into buffer 0 ----
    w_t0[wdstA] = W[(size_t)(k0 + wkl) * 128 + wrest];
    __syncthreads();

    for (int j = 0; j < JOUT; ++j) {
        float* w_t = w_t0 + (j & 1) * 16 * WTB;

        // issue W[j+1] load early; STS after the build (split to hide latency)
        float wnext = 0.f;
        if (j + 1 < JOUT)
            wnext = W[(size_t)((j + 1) * 1152 + k0 + wkl) * 128 + wrest];

        float s0acc[NCH];                     // fused phase1 (it=0) accumulators
        #pragma unroll
        for (int ch = 0; ch < NCH; ++ch) s0acc[ch] = 0.f;

        // ---- pipelined build: 2 rotating prefetch regs, ring of 4 (R9 exact) ----
        {
            float va, vb;
            {
                const float v0 = *XADDR(0);
                const float v1 = *XADDR(1);
                va = *XADDR(2);
                vb = *XADDR(3);
                *XSLOT(0) = v0;
                *XSLOT(1) = v1;
            }

            ulonglong2 Wq0a, Wq0b, Wq1a, Wq1b;
            float clo = 0.f, chi = 0.f;

            #pragma unroll
            for (int s = 0; s < 32; ++s) {
                if (s + 2 < 32) *XSLOT((s + 2) & 3) = va;   // STS for stage s+2
                va = vb;
                if (s + 4 < 32) vb = *XADDR(s + 4);         // LDG for stage s+4
                __syncwarp();

                const int qi = s >> 3, ch = s & 7;
                if (ch == 0) {                // new kl-quarter: refresh W registers
                    const float* wr = w_t + u * WTB + qi * 16;
                    Wq0a = *reinterpret_cast<const ulonglong2*>(wr);
                    Wq0b = *reinterpret_cast<const ulonglong2*>(wr + 4);
                    Wq1a = *reinterpret_cast<const ulonglong2*>(wr + 8);
                    Wq1b = *reinterpret_cast<const ulonglong2*>(wr + 12);
                    clo = c_s[qi * 2]; chi = c_s[qi * 2 + 1];
                }

                const float* xrow = xs + ((s & 3) * 64 + bg) * XST;
                const ulonglong2 X0 = *reinterpret_cast<const ulonglong2*>(xrow);
                const ulonglong2 X1 = *reinterpret_cast<const ulonglong2*>(xrow + 4);
                const ulonglong2 X2 = *reinterpret_cast<const ulonglong2*>(xrow + 8);
                const ulonglong2 X3 = *reinterpret_cast<const ulonglong2*>(xrow + 12);

                float a0, a1;
                {
                    ull acc = f2_mul(X0.x, Wq0a.x);
                    acc = f2_fma(X0.y, Wq0a.y, acc);
                    acc = f2_fma(X1.x, Wq0b.x, acc);
                    acc = f2_fma(X1.y, Wq0b.y, acc);
                    const float2 p = f2_up(acc);
                    a0 = p.x + p.y;
                }
                {
                    ull acc = f2_mul(X2.x, Wq1a.x);
                    acc = f2_fma(X2.y, Wq1a.y, acc);
                    acc = f2_fma(X3.x, Wq1b.x, acc);
                    acc = f2_fma(X3.y, Wq1b.y, acc);
                    const float2 p = f2_up(acc);
                    a1 = p.x + p.y;
                }
                s0acc[ch] = fmaf(a1, chi, fmaf(a0, clo, s0acc[ch]));
                if (ch < SQ) {
                    const int off = (u * 8 + qi * 2) ^ (u & 4);
                    *reinterpret_cast<float2*>(uh_s + (ch * 64 + bg) * UHB + off)
                        = make_float2(a0, a1);
                } else {
                    uhr[ch - SQ][qi] = f2_pk(a0, a1);
                }
            }
        }

        // fused phase1 (it=0) store
        #pragma unroll
        for (int ch = 0; ch < NCH; ++ch)
            __stcg(&g_spart[((size_t)cta * BATCH + ch * 64 + bg) * 16 + u], s0acc[ch]);

        // W[j+1] into alternate buffer; >=2 grid barriers before its first read
        if (j + 1 < JOUT)
            w_t0[((j + 1) & 1) * 16 * WTB + wdstA] = wnext;

        for (int it = 0; it < ITERS; ++it) {
            const bool last = (j == JOUT - 1) && (it == ITERS - 1);

            // ---------- phase 1 (it>=1): partial s over this CTA's 8 k's ----------
            if (it > 0) {
                const ull c01 = f2_pk(c_s[0], c_s[1]);
                const ull c23 = f2_pk(c_s[2], c_s[3]);
                const ull c45 = f2_pk(c_s[4], c_s[5]);
                const ull c67 = f2_pk(c_s[6], c_s[7]);
                #pragma unroll
                for (int q = 0; q < SQ; ++q) {
                    const int b = q * 64 + bg;
                    const float* src = uh_s + b * UHB;
                    const ulonglong2 A  = *reinterpret_cast<const ulonglong2*>(src + uoff(u, 0));
                    const ulonglong2 Bv = *reinterpret_cast<const ulonglong2*>(src + uoff(u, 1));
                    ull s0 = f2_mul(A.x, c01);
                    ull s1 = f2_mul(A.y, c23);
                    s0 = f2_fma(Bv.x, c45, s0);
                    s1 = f2_fma(Bv.y, c67, s1);
                    const float2 p = f2_up(f2_add(s0, s1));
                    __stcg(&g_spart[((size_t)cta * BATCH + b) * 16 + u], p.x + p.y);
                }
                #pragma unroll
                for (int q = 0; q < RQ; ++q) {
                    const int b = SB + q * 64 + bg;
                    ull s0 = f2_mul(uhr[q][0], c01);
                    ull s1 = f2_mul(uhr[q][1], c23);
                    s0 = f2_fma(uhr[q][2], c45, s0);
                    s1 = f2_fma(uhr[q][3], c67, s1);
                    const float2 p = f2_up(f2_add(s0, s1));
                    __stcg(&g_spart[((size_t)cta * BATCH + b) * 16 + u], p.x + p.y);
                }
            }
            ++ep; grid_barrier(base + ep, inc);

            // ---------- phase 2: reduce 144 partials, squash -> v ----------
            if (cta < 128) {
                const int bl  = (t >> 4) & 3;
                const int ch2 = t >> 6;                     // 0..15
                const int b   = cta * 4 + bl;
                float p = 0.f;
                for (int i = ch2; i < NCTA; i += 16)
                    p += __ldcg(&g_spart[((size_t)i * BATCH + b) * 16 + u]);
                scratch[ch2 * 64 + bl * 16 + u] = p;
                __syncthreads();
                if (t < 64) {
                    float s = 0.f;
                    #pragma unroll
                    for (int c2 = 0; c2 < 16; ++c2) s += scratch[c2 * 64 + t];
                    float sq = s * s;
                    #pragma unroll
                    for (int m = 8; m >= 1; m >>= 1)
                        sq += __shfl_xor_sync(0xffffffffu, sq, m);
                    const float v = s * sq / ((1.f + sq) * (sqrtf(sq) + 1e-7f));
                    const int bb = cta * 4 + (t >> 4);
                    if (!last)
                        __stcg(&g_v[bb * 16 + (t & 15)], v);
                    if (it == ITERS - 1)
                        out[((size_t)bb * JOUT + j) * 16 + (t & 15)] = v;
                }
            }
            if (last) break;                   // final v written; no p3 needed
            ++ep; grid_barrier(base + ep, inc);

            // ---------- phase 3: agree, b_IJ update, next c (CTA-local) ----------
            {
                ull ag0 = 0ull, ag1 = 0ull, ag2 = 0ull, ag3 = 0ull;
                #pragma unroll
                for (int q = 0; q < SQ; ++q) {
                    const int b = q * 64 + bg;
                    const float vv = __ldcg(&g_v[b * 16 + u]);
                    const ull vp = f2_pk(vv, vv);
                    const float* src = uh_s + b * UHB;
                    const ulonglong2 A  = *reinterpret_cast<const ulonglong2*>(src + uoff(u, 0));
                    const ulonglong2 Bv = *reinterpret_cast<const ulonglong2*>(src + uoff(u, 1));
                    ag0 = f2_fma(A.x,  vp, ag0);
                    ag1 = f2_fma(A.y,  vp, ag1);
                    ag2 = f2_fma(Bv.x, vp, ag2);
                    ag3 = f2_fma(Bv.y, vp, ag3);
                }
                #pragma unroll
                for (int q = 0; q < RQ; ++q) {
                    const int b = SB + q * 64 + bg;
                    const float vv = __ldcg(&g_v[b * 16 + u]);
                    const ull vp = f2_pk(vv, vv);
                    ag0 = f2_fma(uhr[q][0], vp, ag0);
                    ag1 = f2_fma(uhr[q][1], vp, ag1);
                    ag2 = f2_fma(uhr[q][2], vp, ag2);
                    ag3 = f2_fma(uhr[q][3], vp, ag3);
                }
                float ag[8];
                { float2 p;
                  p = f2_up(ag0); ag[0] = p.x; ag[1] = p.y;
                  p = f2_up(ag1); ag[2] = p.x; ag[3] = p.y;
                  p = f2_up(ag2); ag[4] = p.x; ag[5] = p.y;
                  p = f2_up(ag3); ag[6] = p.x; ag[7] = p.y; }
                #pragma unroll
                for (int kl = 0; kl < KL; ++kl) {
                    float v = ag[kl];
                    #pragma unroll
                    for (int m = 16; m >= 1; m >>= 1)
                        v += __shfl_xor_sync(0xffffffffu, v, m);
                    if (lane == 0) scratch[warp * KL + kl] = v;
                }
                __syncthreads();
                if (t < KL) {
                    float s = 0.f;
                    #pragma unroll
                    for (int w2 = 0; w2 < 32; ++w2) s += scratch[w2 * KL + t];
                    bs[t * JOUT + j] += s;
                    const int jn = (it < ITERS - 1) ? j : j + 1;
                    if (jn < JOUT) {
                        float m = bs[t * JOUT];
                        #pragma unroll
                        for (int jj = 1; jj < JOUT; ++jj)
                            m = fmaxf(m, bs[t * JOUT + jj]);
                        float den = 0.f, num = 0.f;
                        #pragma unroll
                        for (int jj = 0; jj < JOUT; ++jj) {
                            const float e = expf(bs[t * JOUT + jj] - m);
                            den += e;
                            if (jj == jn) num = e;
                        }
                        c_s[t] = num / den;
                    }
                }
                __syncthreads();
            }
        } // it
    } // j
}

extern "C" void kernel_launch(void* const* d_in, const int* in_sizes, int n_in,
                              void* d_out, int out_size) {
    const float* x = (const float*)d_in[0];   // [512,1152,8,1]
    const float* W = (const float*)d_in[1];   // [10,1152,8,16]
    float* out = (float*)d_out;               // [512,10,16,1]
    (void)in_sizes; (void)n_in; (void)out_size;

    cudaFuncSetAttribute(caps_routing_kernel,
                         cudaFuncAttributeMaxDynamicSharedMemorySize, SMEM_BYTES);
    caps_routing_kernel<<<NCTA, THREADS, SMEM_BYTES>>>(x, W, out);
}

// round 17
// speedup vs baseline: 1.5696x; 1.5696x over previous
#include <cuda_runtime.h>

// CapsNet dynamic routing, persistent kernel, round 17.
// = R15 EXACTLY (331.9us best: R9 compute path + minimal-fence barrier:
//   release-atomic arrival, acquire-load polling, per-barrier gen reload)
// + ONE change on the flip critical path: arrivals are atom.add.ACQ_REL
//   (flipper's RMW acquires the release-chain of all prior arrivals), so the
//   flipper's mid __threadfence() is deleted -- its st.release of the sense
//   carries cumulativity over everything it acquired. One fewer gpu-scope
//   MEMBAR on the path all 143 waiters serialize behind, x59 barriers.
// (R16's local-generation tracking caused an unexplained 508us regression
//  and is fully reverted: gen is re-loaded from g_sense each barrier.)

#define NCTA 144
#define THREADS 1024
#define KL 8
#define BATCH 512
#define JOUT 10
#define ITERS 3
#define SB 384          // b's with u_hat in smem
#define SQ 6            // smem chunks of 64 b
#define RQ 2            // register chunks of 64 b
#define NCH 8           // total chunks
#define UHB 128         // floats per b row (swizzled, no pad)
#define WTB 68          // w_t row stride
#define XST 20          // xs row stride (16B-aligned, low-conflict)

#define SMEM_FLOATS (SB*UHB + 4*64*XST + 2*16*WTB + KL*JOUT + KL + 1024)
#define SMEM_BYTES (SMEM_FLOATS * 4)

typedef unsigned long long ull;

__device__ float g_spart[NCTA * BATCH * 16];
__device__ float g_v[BATCH * 16];
__device__ unsigned g_count;
__device__ unsigned g_sense;

__device__ __forceinline__ ull f2_pk(float lo, float hi) {
    ull r; asm("mov.b64 %0,{%1,%2};" : "=l"(r) : "f"(lo), "f"(hi)); return r;
}
__device__ __forceinline__ float2 f2_up(ull a) {
    float2 r; asm("mov.b64 {%0,%1},%2;" : "=f"(r.x), "=f"(r.y) : "l"(a)); return r;
}
__device__ __forceinline__ ull f2_fma(ull a, ull b, ull c) {
    ull d; asm("fma.rn.f32x2 %0,%1,%2,%3;" : "=l"(d) : "l"(a), "l"(b), "l"(c)); return d;
}
__device__ __forceinline__ ull f2_mul(ull a, ull b) {
    ull d; asm("mul.rn.f32x2 %0,%1,%2;" : "=l"(d) : "l"(a), "l"(b)); return d;
}
__device__ __forceinline__ ull f2_add(ull a, ull b) {
    ull d; asm("add.rn.f32x2 %0,%1,%2;" : "=l"(d) : "l"(a), "l"(b)); return d;
}

// swizzled word offset of the h-th float4 (h=0: kl0-3, h=1: kl4-7) for vector idx u
__device__ __forceinline__ int uoff(int u, int h) { return (u * 8 + h * 4) ^ (u & 4); }

// Flat grid barrier, minimal-fence form (R15) with acq_rel arrivals.
// Arrival: atom.add.acq_rel.gpu -- releases this CTA's writes AND (for the
//          eventual flipper) acquires the release-chain of prior arrivals.
// Flip:    count reset, then st.release of sense: orders the reset and,
//          by cumulativity over the acquired chain, all CTAs' data writes.
// Wait:    ld.acquire.gpu poll + nanosleep backoff (synchronizes with release).
// Monotonic sense + self-resetting count -> graph-replay safe.
__device__ __forceinline__ void grid_barrier() {
    __syncthreads();
    if (threadIdx.x == 0) {
        unsigned gen;
        asm volatile("ld.global.u32 %0, [%1];" : "=r"(gen) : "l"(&g_sense));
        unsigned old;
        asm volatile("atom.add.acq_rel.gpu.global.u32 %0, [%1], 1;"
                     : "=r"(old) : "l"(&g_count) : "memory");
        if (old == NCTA - 1) {
            g_count = 0;
            asm volatile("st.release.gpu.global.u32 [%0], %1;"
                         :: "l"(&g_sense), "r"(gen + 1u) : "memory");
        } else {
            unsigned s;
            for (;;) {
                asm volatile("ld.acquire.gpu.global.u32 %0, [%1];"
                             : "=r"(s) : "l"(&g_sense) : "memory");
                if (s != gen) break;
                __nanosleep(64);
            }
        }
    }
    __syncthreads();
}

__global__ void __launch_bounds__(THREADS, 1)
caps_routing_kernel(const float* __restrict__ x,   // [512,1152,8]
                    const float* __restrict__ W,   // [10,1152,8,16]
                    float* __restrict__ out)       // [512,10,16]
{
    extern __shared__ float sm[];
    float* uh_s    = sm;                     // SB*UHB
    float* xs      = uh_s + SB * UHB;        // 4-buffer x staging ring
    float* w_t0    = xs + 4 * 64 * XST;      // 2 x 16*WTB (double-buffered W)
    float* bs      = w_t0 + 2 * 16 * WTB;    // KL*JOUT b_IJ rows
    float* c_s     = bs + KL * JOUT;         // KL coupling coeffs
    float* scratch = c_s + KL;               // 1024 reduction scratch

    const int t    = threadIdx.x;
    const int cta  = blockIdx.x;
    const int k0   = cta * KL;
    const int u    = t & 15;
    const int bg   = t >> 4;                 // 0..63
    const int lane = t & 31;
    const int warp = t >> 5;

    ull uhr[RQ][4];                          // register u_hat for b in [384,512)

    for (int i = t; i < KL * JOUT; i += THREADS) bs[i] = 0.f;
    if (t < KL) c_s[t] = 0.1f;               // softmax(0) over 10
    __syncthreads();

    // per-thread x element address base: x[b=bg(+64*ch), k0.., qi*16+u]
    const float* xbase = x + ((size_t)bg * 1152 + k0) * 8 + u;
    #define XADDR(s_) (xbase + (size_t)((s_) & 7) * 64 * 9216 + ((s_) >> 3) * 16)
    #define XSLOT(p_) (xs + (((p_) * 64) + bg) * XST + u)

    // W transpose indices (KL*128 == THREADS: one element per thread per j)
    const int wkl = t >> 7, wrest = t & 127;
    const int wdstA = (wrest & 15) * WTB + wkl * 8 + (wrest >> 4);

    // ---- load W[j=0] into buffer 0 ----
    w_t0[wdstA] = W[(size_t)(k0 + wkl) * 128 + wrest];
    __syncthreads();

    for (int j = 0; j < JOUT; ++j) {
        float* w_t = w_t0 + (j & 1) * 16 * WTB;

        // issue W[j+1] load early; STS after the build (split to hide latency)
        float wnext = 0.f;
        if (j + 1 < JOUT)
            wnext = W[(size_t)((j + 1) * 1152 + k0 + wkl) * 128 + wrest];

        float s0acc[NCH];                     // fused phase1 (it=0) accumulators
        #pragma unroll
        for (int ch = 0; ch < NCH; ++ch) s0acc[ch] = 0.f;

        // ---- pipelined build: 2 rotating prefetch regs, ring of 4 (R9 exact) ----
        {
            float va, vb;
            {
                const float v0 = *XADDR(0);
                const float v1 = *XADDR(1);
                va = *XADDR(2);
                vb = *XADDR(3);
                *XSLOT(0) = v0;
                *XSLOT(1) = v1;
            }

            ulonglong2 Wq0a, Wq0b, Wq1a, Wq1b;
            float clo = 0.f, chi = 0.f;

            #pragma unroll
            for (int s = 0; s < 32; ++s) {
                if (s + 2 < 32) *XSLOT((s + 2) & 3) = va;   // STS for stage s+2
                va = vb;
                if (s + 4 < 32) vb = *XADDR(s + 4);         // LDG for stage s+4
                __syncwarp();

                const int qi = s >> 3, ch = s & 7;
                if (ch == 0) {                // new kl-quarter: refresh W registers
                    const float* wr = w_t + u * WTB + qi * 16;
                    Wq0a = *reinterpret_cast<const ulonglong2*>(wr);
                    Wq0b = *reinterpret_cast<const ulonglong2*>(wr + 4);
                    Wq1a = *reinterpret_cast<const ulonglong2*>(wr + 8);
                    Wq1b = *reinterpret_cast<const ulonglong2*>(wr + 12);
                    clo = c_s[qi * 2]; chi = c_s[qi * 2 + 1];
                }

                const float* xrow = xs + ((s & 3) * 64 + bg) * XST;
                const ulonglong2 X0 = *reinterpret_cast<const ulonglong2*>(xrow);
                const ulonglong2 X1 = *reinterpret_cast<const ulonglong2*>(xrow + 4);
                const ulonglong2 X2 = *reinterpret_cast<const ulonglong2*>(xrow + 8);
                const ulonglong2 X3 = *reinterpret_cast<const ulonglong2*>(xrow + 12);

                float a0, a1;
                {
                    ull acc = f2_mul(X0.x, Wq0a.x);
                    acc = f2_fma(X0.y, Wq0a.y, acc);
                    acc = f2_fma(X1.x, Wq0b.x, acc);
                    acc = f2_fma(X1.y, Wq0b.y, acc);
                    const float2 p = f2_up(acc);
                    a0 = p.x + p.y;
                }
                {
                    ull acc = f2_mul(X2.x, Wq1a.x);
                    acc = f2_fma(X2.y, Wq1a.y, acc);
                    acc = f2_fma(X3.x, Wq1b.x, acc);
                    acc = f2_fma(X3.y, Wq1b.y, acc);
                    const float2 p = f2_up(acc);
                    a1 = p.x + p.y;
                }
                s0acc[ch] = fmaf(a1, chi, fmaf(a0, clo, s0acc[ch]));
                if (ch < SQ) {
                    const int off = (u * 8 + qi * 2) ^ (u & 4);
                    *reinterpret_cast<float2*>(uh_s + (ch * 64 + bg) * UHB + off)
                        = make_float2(a0, a1);
                } else {
                    uhr[ch - SQ][qi] = f2_pk(a0, a1);
                }
            }
        }

        // fused phase1 (it=0) store
        #pragma unroll
        for (int ch = 0; ch < NCH; ++ch)
            __stcg(&g_spart[((size_t)cta * BATCH + ch * 64 + bg) * 16 + u], s0acc[ch]);

        // W[j+1] into alternate buffer; >=2 grid barriers before its first read
        if (j + 1 < JOUT)
            w_t0[((j + 1) & 1) * 16 * WTB + wdstA] = wnext;

        for (int it = 0; it < ITERS; ++it) {
            const bool last = (j == JOUT - 1) && (it == ITERS - 1);

            // ---------- phase 1 (it>=1): partial s over this CTA's 8 k's ----------
            if (it > 0) {
                const ull c01 = f2_pk(c_s[0], c_s[1]);
                const ull c23 = f2_pk(c_s[2], c_s[3]);
                const ull c45 = f2_pk(c_s[4], c_s[5]);
                const ull c67 = f2_pk(c_s[6], c_s[7]);
                #pragma unroll
                for (int q = 0; q < SQ; ++q) {
                    const int b = q * 64 + bg;
                    const float* src = uh_s + b * UHB;
                    const ulonglong2 A  = *reinterpret_cast<const ulonglong2*>(src + uoff(u, 0));
                    const ulonglong2 Bv = *reinterpret_cast<const ulonglong2*>(src + uoff(u, 1));
                    ull s0 = f2_mul(A.x, c01);
                    ull s1 = f2_mul(A.y, c23);
                    s0 = f2_fma(Bv.x, c45, s0);
                    s1 = f2_fma(Bv.y, c67, s1);
                    const float2 p = f2_up(f2_add(s0, s1));
                    __stcg(&g_spart[((size_t)cta * BATCH + b) * 16 + u], p.x + p.y);
                }
                #pragma unroll
                for (int q = 0; q < RQ; ++q) {
                    const int b = SB + q * 64 + bg;
                    ull s0 = f2_mul(uhr[q][0], c01);
                    ull s1 = f2_mul(uhr[q][1], c23);
                    s0 = f2_fma(uhr[q][2], c45, s0);
                    s1 = f2_fma(uhr[q][3], c67, s1);
                    const float2 p = f2_up(f2_add(s0, s1));
                    __stcg(&g_spart[((size_t)cta * BATCH + b) * 16 + u], p.x + p.y);
                }
            }
            grid_barrier();

            // ---------- phase 2: reduce 144 partials, squash -> v ----------
            if (cta < 128) {
                const int bl  = (t >> 4) & 3;
                const int ch2 = t >> 6;                     // 0..15
                const int b   = cta * 4 + bl;
                float p = 0.f;
                for (int i = ch2; i < NCTA; i += 16)
                    p += __ldcg(&g_spart[((size_t)i * BATCH + b) * 16 + u]);
                scratch[ch2 * 64 + bl * 16 + u] = p;
                __syncthreads();
                if (t < 64) {
                    float s = 0.f;
                    #pragma unroll
                    for (int c2 = 0; c2 < 16; ++c2) s += scratch[c2 * 64 + t];
                    float sq = s * s;
                    #pragma unroll
                    for (int m = 8; m >= 1; m >>= 1)
                        sq += __shfl_xor_sync(0xffffffffu, sq, m);
                    const float v = s * sq / ((1.f + sq) * (sqrtf(sq) + 1e-7f));
                    const int bb = cta * 4 + (t >> 4);
                    if (!last)
                        __stcg(&g_v[bb * 16 + (t & 15)], v);
                    if (it == ITERS - 1)
                        out[((size_t)bb * JOUT + j) * 16 + (t & 15)] = v;
                }
            }
            if (last) break;                   // final v written; no p3 needed
            grid_barrier();

            // ---------- phase 3: agree, b_IJ update, next c (CTA-local) ----------
            {
                ull ag0 = 0ull, ag1 = 0ull, ag2 = 0ull, ag3 = 0ull;
                #pragma unroll
                for (int q = 0; q < SQ; ++q) {
                    const int b = q * 64 + bg;
                    const float vv = __ldcg(&g_v[b * 16 + u]);
                    const ull vp = f2_pk(vv, vv);
                    const float* src = uh_s + b * UHB;
                    const ulonglong2 A  = *reinterpret_cast<const ulonglong2*>(src + uoff(u, 0));
                    const ulonglong2 Bv = *reinterpret_cast<const ulonglong2*>(src + uoff(u, 1));
                    ag0 = f2_fma(A.x,  vp, ag0);
                    ag1 = f2_fma(A.y,  vp, ag1);
                    ag2 = f2_fma(Bv.x, vp, ag2);
                    ag3 = f2_fma(Bv.y, vp, ag3);
                }
                #pragma unroll
                for (int q = 0; q < RQ; ++q) {
                    const int b = SB + q * 64 + bg;
                    const float vv = __ldcg(&g_v[b * 16 + u]);
                    const ull vp = f2_pk(vv, vv);
                    ag0 = f2_fma(uhr[q][0], vp, ag0);
                    ag1 = f2_fma(uhr[q][1], vp, ag1);
                    ag2 = f2_fma(uhr[q][2], vp, ag2);
                    ag3 = f2_fma(uhr[q][3], vp, ag3);
                }
                float ag[8];
                { float2 p;
                  p = f2_up(ag0); ag[0] = p.x; ag[1] = p.y;
                  p = f2_up(ag1); ag[2] = p.x; ag[3] = p.y;
                  p = f2_up(ag2); ag[4] = p.x; ag[5] = p.y;
                  p = f2_up(ag3); ag[6] = p.x; ag[7] = p.y; }
                #pragma unroll
                for (int kl = 0; kl < KL; ++kl) {
                    float v = ag[kl];
                    #pragma unroll
                    for (int m = 16; m >= 1; m >>= 1)
                        v += __shfl_xor_sync(0xffffffffu, v, m);
                    if (lane == 0) scratch[warp * KL + kl] = v;
                }
                __syncthreads();
                if (t < KL) {
                    float s = 0.f;
                    #pragma unroll
                    for (int w2 = 0; w2 < 32; ++w2) s += scratch[w2 * KL + t];
                    bs[t * JOUT + j] += s;
                    const int jn = (it < ITERS - 1) ? j : j + 1;
                    if (jn < JOUT) {
                        float m = bs[t * JOUT];
                        #pragma unroll
                        for (int jj = 1; jj < JOUT; ++jj)
                            m = fmaxf(m, bs[t * JOUT + jj]);
                        float den = 0.f, num = 0.f;
                        #pragma unroll
                        for (int jj = 0; jj < JOUT; ++jj) {
                            const float e = expf(bs[t * JOUT + jj] - m);
                            den += e;
                            if (jj == jn) num = e;
                        }
                        c_s[t] = num / den;
                    }
                }
                __syncthreads();
            }
        } // it
    } // j
}

extern "C" void kernel_launch(void* const* d_in, const int* in_sizes, int n_in,
                              void* d_out, int out_size) {
    const float* x = (const float*)d_in[0];   // [512,1152,8,1]
    const float* W = (const float*)d_in[1];   // [10,1152,8,16]
    float* out = (float*)d_out;               // [512,10,16,1]
    (void)in_sizes; (void)n_in; (void)out_size;

    cudaFuncSetAttribute(caps_routing_kernel,
                         cudaFuncAttributeMaxDynamicSharedMemorySize, SMEM_BYTES);
    caps_routing_kernel<<<NCTA, THREADS, SMEM_BYTES>>>(x, W, out);
}